// round 1
// baseline (speedup 1.0000x reference)
#include <cuda_runtime.h>
#include <cuda_fp16.h>
#include <cstdint>

// Problem dims (fixed by the dataset)
#define M_DIM 4096
#define K_DIM 4096
#define N_DIM 12288
#define TILES_T (K_DIM / 16)   // 256 packed tile-rows of B

// ---------------------------------------------------------------------------
// Scratch (device globals: allocation-free per harness rules)
// ---------------------------------------------------------------------------
__device__ __half g_A[16777216];   // A in fp16, [M, K] row-major (32 MB)
__device__ __half g_W[50331648];   // dequantized W in fp16, [K, N] row-major (96 MB)

// ---------------------------------------------------------------------------
// Kernel 1: A fp32 -> fp16
// ---------------------------------------------------------------------------
__global__ void convA_kernel(const float* __restrict__ A, __half* __restrict__ Ah) {
    int i = blockIdx.x * blockDim.x + threadIdx.x;          // one float4 per thread
    const float4 v = reinterpret_cast<const float4*>(A)[i];
    __half2 h0 = __floats2half2_rn(v.x, v.y);
    __half2 h1 = __floats2half2_rn(v.z, v.w);
    __half2* dst = reinterpret_cast<__half2*>(Ah) + 2 * i;
    dst[0] = h0;
    dst[1] = h1;
}

// ---------------------------------------------------------------------------
// Kernel 2: dequantize int4 -> fp16 W[K][N]
// B: int32 [TILES_T, 2*N]; each pair of int32 (per output col o) holds 16
// k-values as nibbles: k = t*16 + c*8 + j, value = ((B>>4j)&0xF) - 8.
// scale s[(t>>3)][o]  (group=128 along K == 8 tile-rows).
// Thread (t, o): 2 int32 (coalesced via int2), 16 coalesced fp16 stores.
// ---------------------------------------------------------------------------
__global__ void dequant_kernel(const int* __restrict__ B,
                               const float* __restrict__ s,
                               __half* __restrict__ W) {
    int idx = blockIdx.x * blockDim.x + threadIdx.x;
    int t = idx / N_DIM;
    int o = idx - t * N_DIM;
    int2 packed = reinterpret_cast<const int2*>(B)[(size_t)t * N_DIM + o];
    float scale = s[(t >> 3) * N_DIM + o];
    int vals[2] = {packed.x, packed.y};
    size_t base = (size_t)(t * 16) * N_DIM + o;
#pragma unroll
    for (int c = 0; c < 2; c++) {
#pragma unroll
        for (int j = 0; j < 8; j++) {
            int q = (vals[c] >> (4 * j)) & 0xF;
            float w = (float)(q - 8) * scale;
            W[base + (size_t)(c * 8 + j) * N_DIM] = __float2half_rn(w);
        }
    }
}

// ---------------------------------------------------------------------------
// Kernel 3: GEMM  C = Ah @ W + bias   (fp16 in, fp32 accumulate/out)
// 128x128x32 CTA tile, 256 threads = 8 warps (4 m x 2 n), warp tile 32x64,
// mma.sync.m16n8k16, 4-stage cp.async pipeline, padded smem (conflict-free).
// ---------------------------------------------------------------------------
constexpr int BM = 128, BN = 128, BK = 32;
constexpr int STAGES = 4;
constexpr int AS_LD = BK + 8;            // 40 halfs/row  (80B: 16B-aligned, conflict-free)
constexpr int BS_LD = BN + 8;            // 136 halfs/row (272B)
constexpr int A_STAGE = BM * AS_LD;      // 5120 halfs
constexpr int B_STAGE = BK * BS_LD;      // 4352 halfs
constexpr int SMEM_BYTES = STAGES * (A_STAGE + B_STAGE) * 2;  // 75776
constexpr int KT = K_DIM / BK;           // 128 mainloop iterations

__device__ __forceinline__ uint32_t smem_u32(const void* p) {
    return (uint32_t)__cvta_generic_to_shared(p);
}
__device__ __forceinline__ void cp_async16(void* sp, const void* gp) {
    asm volatile("cp.async.cg.shared.global [%0], [%1], 16;\n"
                 :: "r"(smem_u32(sp)), "l"(gp));
}
__device__ __forceinline__ void ldsm4(uint32_t* r, const __half* p) {
    asm volatile("ldmatrix.sync.aligned.m8n8.x4.shared.b16 {%0,%1,%2,%3}, [%4];"
                 : "=r"(r[0]), "=r"(r[1]), "=r"(r[2]), "=r"(r[3])
                 : "r"(smem_u32(p)));
}
__device__ __forceinline__ void ldsm4t(uint32_t* r, const __half* p) {
    asm volatile("ldmatrix.sync.aligned.m8n8.x4.trans.shared.b16 {%0,%1,%2,%3}, [%4];"
                 : "=r"(r[0]), "=r"(r[1]), "=r"(r[2]), "=r"(r[3])
                 : "r"(smem_u32(p)));
}
__device__ __forceinline__ void mma16816(float* c, const uint32_t* a, const uint32_t* b) {
    asm volatile("mma.sync.aligned.m16n8k16.row.col.f32.f16.f16.f32 "
                 "{%0,%1,%2,%3}, {%4,%5,%6,%7}, {%8,%9}, {%0,%1,%2,%3};"
                 : "+f"(c[0]), "+f"(c[1]), "+f"(c[2]), "+f"(c[3])
                 : "r"(a[0]), "r"(a[1]), "r"(a[2]), "r"(a[3]),
                   "r"(b[0]), "r"(b[1]));
}

__device__ __forceinline__ void load_stage(int stage, int kt, int m0, int n0,
                                           const __half* __restrict__ Ah,
                                           const __half* __restrict__ Wh,
                                           __half* As, __half* Bs, int tid) {
    int k0 = kt * BK;
    // A tile: 128x32 halfs = 512 chunks of 16B (4 chunks per row)
#pragma unroll
    for (int i = 0; i < 2; i++) {
        int cid = tid + 256 * i;
        int row = cid >> 2;
        int col = (cid & 3) * 8;
        cp_async16(&As[stage * A_STAGE + row * AS_LD + col],
                   &Ah[(size_t)(m0 + row) * K_DIM + k0 + col]);
    }
    // B tile: 32x128 halfs = 512 chunks (16 chunks per row, fully coalesced)
#pragma unroll
    for (int i = 0; i < 2; i++) {
        int cid = tid + 256 * i;
        int row = cid >> 4;
        int col = (cid & 15) * 8;
        cp_async16(&Bs[stage * B_STAGE + row * BS_LD + col],
                   &Wh[(size_t)(k0 + row) * N_DIM + n0 + col]);
    }
}

__global__ __launch_bounds__(256, 2)
void gemm_f16_kernel(const __half* __restrict__ Ah, const __half* __restrict__ Wh,
                     const float* __restrict__ bias, float* __restrict__ C) {
    extern __shared__ __half smem[];
    __half* As = smem;
    __half* Bs = smem + STAGES * A_STAGE;

    // grid swizzle (GROUP_M=8 supertiles for L2 reuse)
    constexpr int GRID_M = M_DIM / BM;   // 32
    constexpr int GRID_N = N_DIM / BN;   // 96
    constexpr int GROUP_M = 8;
    int pid = blockIdx.x;
    int group_size = GROUP_M * GRID_N;
    int gid = pid / group_size;
    int first_m = gid * GROUP_M;
    int gsz = (GRID_M - first_m < GROUP_M) ? (GRID_M - first_m) : GROUP_M;
    int bm = first_m + (pid % gsz);
    int bn = (pid % group_size) / gsz;
    int m0 = bm * BM, n0 = bn * BN;

    int tid = threadIdx.x;
    int lane = tid & 31;
    int warp = tid >> 5;
    int wm = warp & 3;             // 4 warps along M
    int wn = warp >> 2;            // 2 warps along N
    int m_warp = wm * 32;
    int n_warp = wn * 64;

    float acc[2][8][4];
#pragma unroll
    for (int i = 0; i < 2; i++)
#pragma unroll
        for (int j = 0; j < 8; j++)
#pragma unroll
            for (int k = 0; k < 4; k++) acc[i][j][k] = 0.f;

    // prologue: fill STAGES-1 stages
#pragma unroll
    for (int s = 0; s < STAGES - 1; s++) {
        load_stage(s, s, m0, n0, Ah, Wh, As, Bs, tid);
        asm volatile("cp.async.commit_group;\n");
    }

    for (int kt = 0; kt < KT; kt++) {
        asm volatile("cp.async.wait_group %0;\n" :: "n"(STAGES - 2));
        __syncthreads();

        // issue next tile's loads (overwrites buffer consumed last iteration)
        if (kt + STAGES - 1 < KT)
            load_stage((kt + STAGES - 1) % STAGES, kt + STAGES - 1, m0, n0,
                       Ah, Wh, As, Bs, tid);
        asm volatile("cp.async.commit_group;\n");

        const __half* As_s = As + (kt % STAGES) * A_STAGE;
        const __half* Bs_s = Bs + (kt % STAGES) * B_STAGE;

#pragma unroll
        for (int ks = 0; ks < 2; ks++) {
            int k16 = ks * 16;
            uint32_t a[2][4];
#pragma unroll
            for (int mt = 0; mt < 2; mt++)
                ldsm4(a[mt], &As_s[(m_warp + mt * 16 + (lane & 15)) * AS_LD +
                                   k16 + (lane >> 4) * 8]);
            uint32_t b[8][2];
#pragma unroll
            for (int nt2 = 0; nt2 < 4; nt2++) {
                int g = lane >> 3;  // 0..3: (k-half, n-half) of the 16x16 block
                uint32_t r[4];
                ldsm4t(r, &Bs_s[(k16 + (g & 1) * 8 + (lane & 7)) * BS_LD +
                                n_warp + nt2 * 16 + (g >> 1) * 8]);
                b[nt2 * 2][0] = r[0]; b[nt2 * 2][1] = r[1];
                b[nt2 * 2 + 1][0] = r[2]; b[nt2 * 2 + 1][1] = r[3];
            }
#pragma unroll
            for (int mt = 0; mt < 2; mt++)
#pragma unroll
                for (int nt = 0; nt < 8; nt++)
                    mma16816(acc[mt][nt], a[mt], b[nt]);
        }
    }

    // epilogue: C = acc + bias (fp32)
#pragma unroll
    for (int mt = 0; mt < 2; mt++) {
#pragma unroll
        for (int nt = 0; nt < 8; nt++) {
            int row = m0 + m_warp + mt * 16 + (lane >> 2);
            int col = n0 + n_warp + nt * 8 + (lane & 3) * 2;
            float2 bv = *reinterpret_cast<const float2*>(&bias[col]);
            float2 v0 = make_float2(acc[mt][nt][0] + bv.x, acc[mt][nt][1] + bv.y);
            float2 v1 = make_float2(acc[mt][nt][2] + bv.x, acc[mt][nt][3] + bv.y);
            *reinterpret_cast<float2*>(&C[(size_t)row * N_DIM + col]) = v0;
            *reinterpret_cast<float2*>(&C[(size_t)(row + 8) * N_DIM + col]) = v1;
        }
    }
}

// ---------------------------------------------------------------------------
// Launch
// ---------------------------------------------------------------------------
extern "C" void kernel_launch(void* const* d_in, const int* in_sizes, int n_in,
                              void* d_out, int out_size) {
    const float* A    = (const float*)d_in[0];
    const int*   B    = (const int*)  d_in[1];
    const float* s    = (const float*)d_in[2];
    const float* bias = (const float*)d_in[3];
    float* C = (float*)d_out;

    __half* Ah = nullptr;
    __half* Wh = nullptr;
    cudaGetSymbolAddress((void**)&Ah, g_A);
    cudaGetSymbolAddress((void**)&Wh, g_W);

    cudaFuncSetAttribute(gemm_f16_kernel,
                         cudaFuncAttributeMaxDynamicSharedMemorySize, SMEM_BYTES);

    // 1) A -> fp16
    convA_kernel<<<(M_DIM * K_DIM / 4) / 256, 256>>>(A, Ah);
    // 2) dequant B -> fp16 W[K][N]
    dequant_kernel<<<(TILES_T * N_DIM) / 256, 256>>>(B, s, Wh);
    // 3) GEMM + bias
    int grid = (M_DIM / BM) * (N_DIM / BN);  // 3072
    gemm_f16_kernel<<<grid, 256, SMEM_BYTES>>>(Ah, Wh, bias, C);
}

// round 5
// speedup vs baseline: 1.0665x; 1.0665x over previous
#include <cuda_runtime.h>
#include <cuda_fp16.h>
#include <cstdint>

#define M_DIM 4096
#define K_DIM 4096
#define N_DIM 12288

// GEMM tiling
constexpr int BM = 128, BN = 256, BK = 32;
constexpr int KT = K_DIM / BK;                 // 128 k-tiles
constexpr int NST = 4;                         // pipeline stages
constexpr int A_TILE = BM * BK * 2;            // 8192 B
constexpr int B_TILE = BN * BK * 2;            // 16384 B
constexpr int STAGE_BYTES = A_TILE + B_TILE;   // 24576
constexpr int SMEM_OFF = 1024;                 // mbarriers live below
constexpr int SMEM_BYTES = SMEM_OFF + NST * STAGE_BYTES;   // 99328

// tile-packed, pre-swizzled operand blobs
__device__ __half g_Apack[(size_t)M_DIM * K_DIM];   // 32 MB, tiles (mb,kt) 128x32
__device__ __half g_Bpack[(size_t)N_DIM * K_DIM];   // 96 MB, tiles (nb,kt) 256x32 [n][k]

// chunk swizzle: 16B chunk c within a 64B row r  ->  c ^ ((r>>1)&3)
// (makes all 8 rows of any 8x8-b16 ldmatrix tile hit distinct bank quads)

// ---------------------------------------------------------------------------
// Pack A: fp32 [M,K] -> fp16 tiles, blob ((mb*128+kt) tiles of 8KB)
// ---------------------------------------------------------------------------
__global__ void convA_kernel(const float* __restrict__ A) {
    int id = blockIdx.x * 256 + threadIdx.x;    // M*512 16B-chunk ids
    int m = id >> 9;
    int ch = id & 511;
    int kt = ch >> 2, c = ch & 3;
    const float4* src = reinterpret_cast<const float4*>(
        A + (size_t)m * K_DIM + kt * 32 + c * 8);
    float4 v0 = src[0], v1 = src[1];
    __half2 h[4];
    h[0] = __floats2half2_rn(v0.x, v0.y);
    h[1] = __floats2half2_rn(v0.z, v0.w);
    h[2] = __floats2half2_rn(v1.x, v1.y);
    h[3] = __floats2half2_rn(v1.z, v1.w);
    int mb = m >> 7, r = m & 127;
    int cs = c ^ ((r >> 1) & 3);
    char* dst = (char*)g_Apack + (size_t)(mb * 128 + kt) * A_TILE + r * 64 + cs * 16;
    *reinterpret_cast<uint4*>(dst) = *reinterpret_cast<uint4*>(h);
}

// ---------------------------------------------------------------------------
// Dequant+pack W: int4 -> fp16 [n][k] tiles, blob ((nb*128+kt) tiles of 16KB)
// thread (t,o): k = t*16 + c8*8 + j, n = o, w = (nib-8)*s[t>>3][o]
// ---------------------------------------------------------------------------
__global__ void dequant_kernel(const int* __restrict__ B, const float* __restrict__ s) {
    int id = blockIdx.x * 256 + threadIdx.x;    // (K/16)*N ids
    int t = id / N_DIM, o = id - t * N_DIM;
    int2 p = reinterpret_cast<const int2*>(B)[(size_t)t * N_DIM + o];
    float sc = s[(t >> 3) * N_DIM + o];
    __half2 h[8];
#pragma unroll
    for (int c8 = 0; c8 < 2; c8++) {
        int v = c8 ? p.y : p.x;
#pragma unroll
        for (int j = 0; j < 4; j++) {
            float w0 = (float)(((v >> (8 * j)) & 0xF) - 8) * sc;
            float w1 = (float)(((v >> (8 * j + 4)) & 0xF) - 8) * sc;
            h[c8 * 4 + j] = __floats2half2_rn(w0, w1);
        }
    }
    int kt = t >> 1;
    int nb = o >> 8, r = o & 255;
    char* tile = (char*)g_Bpack + (size_t)(nb * 128 + kt) * B_TILE;
    int c0 = 2 * (t & 1);
    int xm = (r >> 1) & 3;
    *reinterpret_cast<uint4*>(tile + r * 64 + (c0 ^ xm) * 16)       = *reinterpret_cast<uint4*>(h);
    *reinterpret_cast<uint4*>(tile + r * 64 + ((c0 + 1) ^ xm) * 16) = *reinterpret_cast<uint4*>(h + 4);
}

// ---------------------------------------------------------------------------
// GEMM: C = A @ W^T + bias.  128x256 CTA, 8 warps of 64x64, mma.m16n8k16,
// cp.async.bulk stage loads (2 per kt), mbarrier pipeline, 4 stages.
// ---------------------------------------------------------------------------
__device__ __forceinline__ uint32_t smem_u32(const void* p) {
    return (uint32_t)__cvta_generic_to_shared(p);
}
__device__ __forceinline__ void mbar_init(uint32_t a, uint32_t cnt) {
    asm volatile("mbarrier.init.shared.b64 [%0], %1;" :: "r"(a), "r"(cnt) : "memory");
}
__device__ __forceinline__ void mbar_expect_tx(uint32_t a, uint32_t bytes) {
    asm volatile("mbarrier.arrive.expect_tx.shared.b64 _, [%0], %1;"
                 :: "r"(a), "r"(bytes) : "memory");
}
__device__ __forceinline__ void mbar_wait(uint32_t a, uint32_t parity) {
    asm volatile(
        "{\n\t.reg .pred P;\n"
        "W0_%=:\n\t"
        "mbarrier.try_wait.parity.acquire.cta.shared::cta.b64 P, [%0], %1, 0x989680;\n\t"
        "@P bra.uni W1_%=;\n\t"
        "bra.uni W0_%=;\n\t"
        "W1_%=:\n\t}"
        :: "r"(a), "r"(parity) : "memory");
}
__device__ __forceinline__ void bulk_g2s(uint32_t dst, const void* src,
                                         uint32_t bytes, uint32_t mbar) {
    asm volatile(
        "cp.async.bulk.shared::cluster.global.mbarrier::complete_tx::bytes "
        "[%0], [%1], %2, [%3];"
        :: "r"(dst), "l"(src), "r"(bytes), "r"(mbar) : "memory");
}
__device__ __forceinline__ void ldsm4(uint32_t* r, uint32_t addr) {
    asm volatile("ldmatrix.sync.aligned.m8n8.x4.shared.b16 {%0,%1,%2,%3}, [%4];"
                 : "=r"(r[0]), "=r"(r[1]), "=r"(r[2]), "=r"(r[3]) : "r"(addr));
}
__device__ __forceinline__ void mma16816(float* c, const uint32_t* a, const uint32_t* b) {
    asm volatile("mma.sync.aligned.m16n8k16.row.col.f32.f16.f16.f32 "
                 "{%0,%1,%2,%3}, {%4,%5,%6,%7}, {%8,%9}, {%0,%1,%2,%3};"
                 : "+f"(c[0]), "+f"(c[1]), "+f"(c[2]), "+f"(c[3])
                 : "r"(a[0]), "r"(a[1]), "r"(a[2]), "r"(a[3]),
                   "r"(b[0]), "r"(b[1]));
}

__global__ __launch_bounds__(256, 1)
void gemm_hmma_kernel(const float* __restrict__ bias, float* __restrict__ C) {
    extern __shared__ char smem[];
    uint32_t sb = smem_u32(smem);
    int tid = threadIdx.x, wid = tid >> 5, lane = tid & 31;
    int mb = blockIdx.x & 31, nb = blockIdx.x >> 5;   // mb-fastest: B-tile L2 reuse

    const char* Asrc = (const char*)g_Apack + (size_t)mb * 128 * A_TILE;
    const char* Bsrc = (const char*)g_Bpack + (size_t)nb * 128 * B_TILE;

    if (tid == 0) {
#pragma unroll
        for (int st = 0; st < NST; st++) mbar_init(sb + st * 8, 1);
    }
    __syncthreads();

    auto load_tile = [&](int kt2) {
        int st = kt2 & (NST - 1);
        uint32_t fb = sb + st * 8;
        mbar_expect_tx(fb, STAGE_BYTES);
        uint32_t sdst = sb + SMEM_OFF + st * STAGE_BYTES;
        bulk_g2s(sdst, Asrc + (size_t)kt2 * A_TILE, A_TILE, fb);
        bulk_g2s(sdst + A_TILE, Bsrc + (size_t)kt2 * B_TILE, B_TILE, fb);
    };
    if (tid == 0) {
#pragma unroll
        for (int p = 0; p < NST; p++) load_tile(p);
    }

    // per-thread ldmatrix geometry
    int g = lane >> 3, tr = lane & 7;
    int m_warp = (wid & 1) * 64;
    int n_warp = (wid >> 1) * 64;
    int aRow0 = m_warp + (g & 1) * 8 + tr;   // + mt*16
    int aH = g >> 1;                          // k8-half
    int bRow0 = n_warp + (g >> 1) * 8 + tr;  // + nt2*16
    int bH = g & 1;                           // k8-half

    float acc[4][8][4];
#pragma unroll
    for (int i = 0; i < 4; i++)
#pragma unroll
        for (int j = 0; j < 8; j++)
#pragma unroll
            for (int k = 0; k < 4; k++) acc[i][j][k] = 0.f;

    for (int kt = 0; kt < KT; kt++) {
        int st = kt & (NST - 1);
        mbar_wait(sb + st * 8, (kt >> 2) & 1);
        uint32_t As = sb + SMEM_OFF + st * STAGE_BYTES;
        uint32_t Bs = As + A_TILE;

#pragma unroll
        for (int ks = 0; ks < 2; ks++) {
            uint32_t a[4][4];
#pragma unroll
            for (int mt = 0; mt < 4; mt++) {
                int r = aRow0 + mt * 16;
                int c = (2 * ks + aH) ^ ((r >> 1) & 3);
                ldsm4(a[mt], As + r * 64 + c * 16);
            }
            uint32_t b[8][2];
#pragma unroll
            for (int nt2 = 0; nt2 < 4; nt2++) {
                int r = bRow0 + nt2 * 16;
                int c = (2 * ks + bH) ^ ((r >> 1) & 3);
                uint32_t q[4];
                ldsm4(q, Bs + r * 64 + c * 16);
                b[nt2 * 2][0] = q[0]; b[nt2 * 2][1] = q[1];
                b[nt2 * 2 + 1][0] = q[2]; b[nt2 * 2 + 1][1] = q[3];
            }
#pragma unroll
            for (int mt = 0; mt < 4; mt++)
#pragma unroll
                for (int nt = 0; nt < 8; nt++)
                    mma16816(acc[mt][nt], a[mt], b[nt]);
        }
        __syncthreads();
        if (tid == 0 && kt + NST < KT) load_tile(kt + NST);
    }

    // epilogue: registers -> gmem (+bias)
    int m0 = mb * BM + m_warp;
    int n0 = nb * BN + n_warp;
#pragma unroll
    for (int mt = 0; mt < 4; mt++) {
#pragma unroll
        for (int nt = 0; nt < 8; nt++) {
            int row = m0 + mt * 16 + (lane >> 2);
            int col = n0 + nt * 8 + (lane & 3) * 2;
            float2 bv = *reinterpret_cast<const float2*>(&bias[col]);
            float2 v0 = make_float2(acc[mt][nt][0] + bv.x, acc[mt][nt][1] + bv.y);
            float2 v1 = make_float2(acc[mt][nt][2] + bv.x, acc[mt][nt][3] + bv.y);
            *reinterpret_cast<float2*>(&C[(size_t)row * N_DIM + col]) = v0;
            *reinterpret_cast<float2*>(&C[(size_t)(row + 8) * N_DIM + col]) = v1;
        }
    }
}

// ---------------------------------------------------------------------------
// Launch
// ---------------------------------------------------------------------------
extern "C" void kernel_launch(void* const* d_in, const int* in_sizes, int n_in,
                              void* d_out, int out_size) {
    const float* A    = (const float*)d_in[0];
    const int*   B    = (const int*)  d_in[1];
    const float* s    = (const float*)d_in[2];
    const float* bias = (const float*)d_in[3];
    float* C = (float*)d_out;

    cudaFuncSetAttribute(gemm_hmma_kernel,
                         cudaFuncAttributeMaxDynamicSharedMemorySize, SMEM_BYTES);

    convA_kernel<<<(M_DIM * 512) / 256, 256>>>(A);
    dequant_kernel<<<((K_DIM / 16) * N_DIM) / 256, 256>>>(B, s);

    int grid = (M_DIM / BM) * (N_DIM / BN);   // 32 * 48 = 1536
    gemm_hmma_kernel<<<grid, 256, SMEM_BYTES>>>(bias, C);
}

// round 6
// speedup vs baseline: 1.2296x; 1.1530x over previous
#include <cuda_runtime.h>
#include <cuda_fp16.h>
#include <cstdint>

#define M_DIM 4096
#define K_DIM 4096
#define N_DIM 12288

// GEMM tiling
constexpr int BM = 128, BN = 256, BK = 32;
constexpr int KT = K_DIM / BK;                 // 128 k-tiles per output tile
constexpr int NTILES = (M_DIM / BM) * (N_DIM / BN);   // 1536
constexpr int NST = 8;                         // pipeline stages
constexpr int A_TILE = BM * BK * 2;            // 8192 B
constexpr int B_TILE = BN * BK * 2;            // 16384 B
constexpr int STAGE_BYTES = A_TILE + B_TILE;   // 24576
constexpr int SMEM_OFF = 1024;                 // barriers live below
constexpr int SMEM_BYTES = SMEM_OFF + NST * STAGE_BYTES;   // 197632

// tile-packed, pre-swizzled operand blobs
__device__ __half g_Apack[(size_t)M_DIM * K_DIM];   // 32 MB, tiles (mb,kt) 128x32
__device__ __half g_Bpack[(size_t)N_DIM * K_DIM];   // 96 MB, tiles (nb,kt) 256x32 [n][k]

// chunk swizzle: 16B chunk c within 64B row r -> c ^ ((r>>1)&3)

// ---------------------------------------------------------------------------
// Pack A: fp32 [M,K] -> fp16 tiles, blob ((mb*128+kt) tiles of 8KB)
// ---------------------------------------------------------------------------
__global__ void convA_kernel(const float* __restrict__ A) {
    int id = blockIdx.x * 256 + threadIdx.x;    // M*512 16B-chunk ids
    int m = id >> 9;
    int ch = id & 511;
    int kt = ch >> 2, c = ch & 3;
    const float4* src = reinterpret_cast<const float4*>(
        A + (size_t)m * K_DIM + kt * 32 + c * 8);
    float4 v0 = src[0], v1 = src[1];
    __half2 h[4];
    h[0] = __floats2half2_rn(v0.x, v0.y);
    h[1] = __floats2half2_rn(v0.z, v0.w);
    h[2] = __floats2half2_rn(v1.x, v1.y);
    h[3] = __floats2half2_rn(v1.z, v1.w);
    int mb = m >> 7, r = m & 127;
    int cs = c ^ ((r >> 1) & 3);
    char* dst = (char*)g_Apack + (size_t)(mb * 128 + kt) * A_TILE + r * 64 + cs * 16;
    *reinterpret_cast<uint4*>(dst) = *reinterpret_cast<uint4*>(h);
}

// ---------------------------------------------------------------------------
// Dequant+pack W: int4 -> fp16 [n][k] tiles, blob ((nb*128+kt) tiles of 16KB)
// ---------------------------------------------------------------------------
__global__ void dequant_kernel(const int* __restrict__ B, const float* __restrict__ s) {
    int id = blockIdx.x * 256 + threadIdx.x;    // (K/16)*N ids
    int t = id / N_DIM, o = id - t * N_DIM;
    int2 p = reinterpret_cast<const int2*>(B)[(size_t)t * N_DIM + o];
    float sc = s[(t >> 3) * N_DIM + o];
    __half2 h[8];
#pragma unroll
    for (int c8 = 0; c8 < 2; c8++) {
        int v = c8 ? p.y : p.x;
#pragma unroll
        for (int j = 0; j < 4; j++) {
            float w0 = (float)(((v >> (8 * j)) & 0xF) - 8) * sc;
            float w1 = (float)(((v >> (8 * j + 4)) & 0xF) - 8) * sc;
            h[c8 * 4 + j] = __floats2half2_rn(w0, w1);
        }
    }
    int kt = t >> 1;
    int nb = o >> 8, r = o & 255;
    char* tile = (char*)g_Bpack + (size_t)(nb * 128 + kt) * B_TILE;
    int c0 = 2 * (t & 1);
    int xm = (r >> 1) & 3;
    *reinterpret_cast<uint4*>(tile + r * 64 + (c0 ^ xm) * 16)       = *reinterpret_cast<uint4*>(h);
    *reinterpret_cast<uint4*>(tile + r * 64 + ((c0 + 1) ^ xm) * 16) = *reinterpret_cast<uint4*>(h + 4);
}

// ---------------------------------------------------------------------------
// helpers
// ---------------------------------------------------------------------------
__device__ __forceinline__ uint32_t smem_u32(const void* p) {
    return (uint32_t)__cvta_generic_to_shared(p);
}
__device__ __forceinline__ void mbar_init(uint32_t a, uint32_t cnt) {
    asm volatile("mbarrier.init.shared.b64 [%0], %1;" :: "r"(a), "r"(cnt) : "memory");
}
__device__ __forceinline__ void mbar_expect_tx(uint32_t a, uint32_t bytes) {
    asm volatile("mbarrier.arrive.expect_tx.shared.b64 _, [%0], %1;"
                 :: "r"(a), "r"(bytes) : "memory");
}
__device__ __forceinline__ void mbar_arrive(uint32_t a) {
    asm volatile("mbarrier.arrive.shared.b64 _, [%0];" :: "r"(a) : "memory");
}
__device__ __forceinline__ void mbar_wait(uint32_t a, uint32_t parity) {
    asm volatile(
        "{\n\t.reg .pred P;\n"
        "W0_%=:\n\t"
        "mbarrier.try_wait.parity.acquire.cta.shared::cta.b64 P, [%0], %1, 0x989680;\n\t"
        "@P bra.uni W1_%=;\n\t"
        "bra.uni W0_%=;\n\t"
        "W1_%=:\n\t}"
        :: "r"(a), "r"(parity) : "memory");
}
__device__ __forceinline__ void bulk_g2s(uint32_t dst, const void* src,
                                         uint32_t bytes, uint32_t mbar) {
    asm volatile(
        "cp.async.bulk.shared::cluster.global.mbarrier::complete_tx::bytes "
        "[%0], [%1], %2, [%3];"
        :: "r"(dst), "l"(src), "r"(bytes), "r"(mbar) : "memory");
}
__device__ __forceinline__ void ldsm4(uint32_t* r, uint32_t addr) {
    asm volatile("ldmatrix.sync.aligned.m8n8.x4.shared.b16 {%0,%1,%2,%3}, [%4];"
                 : "=r"(r[0]), "=r"(r[1]), "=r"(r[2]), "=r"(r[3]) : "r"(addr));
}
__device__ __forceinline__ void mma16816(float* c, const uint32_t* a, const uint32_t* b) {
    asm volatile("mma.sync.aligned.m16n8k16.row.col.f32.f16.f16.f32 "
                 "{%0,%1,%2,%3}, {%4,%5,%6,%7}, {%8,%9}, {%0,%1,%2,%3};"
                 : "+f"(c[0]), "+f"(c[1]), "+f"(c[2]), "+f"(c[3])
                 : "r"(a[0]), "r"(a[1]), "r"(a[2]), "r"(a[3]),
                   "r"(b[0]), "r"(b[1]));
}

// ---------------------------------------------------------------------------
// Persistent GEMM: each CTA loops over tiles p, p+P, ... with a pipeline that
// stays primed across tile boundaries. full[st]: tx barrier; empty[st]: 8 warps.
// ---------------------------------------------------------------------------
__global__ __launch_bounds__(256, 1)
void gemm_hmma_kernel(const float* __restrict__ bias, float* __restrict__ C) {
    extern __shared__ char smem[];
    uint32_t sb = smem_u32(smem);
    int tid = threadIdx.x, wid = tid >> 5, lane = tid & 31;
    int p = blockIdx.x, P = gridDim.x;

    if (tid == 0) {
#pragma unroll
        for (int st = 0; st < NST; st++) {
            mbar_init(sb + st * 8, 1);            // full[st], tx-based
            mbar_init(sb + 64 + st * 8, 8);       // empty[st], 8 warp arrivals
        }
    }
    __syncthreads();

    int ntiles = (NTILES - p + P - 1) / P;
    int GI = ntiles * KT;

    // producer: fill global iteration f's stage
    auto fill = [&](int f) {
        int st = f & (NST - 1);
        if (f >= NST) mbar_wait(sb + 64 + st * 8, ((f >> 3) - 1) & 1);
        int tile = p + (f >> 7) * P;
        int ktf = f & 127;
        int mbf = tile & 31, nbf = tile >> 5;
        uint32_t fb = sb + st * 8;
        mbar_expect_tx(fb, STAGE_BYTES);
        uint32_t sdst = sb + SMEM_OFF + st * STAGE_BYTES;
        bulk_g2s(sdst, (const char*)g_Apack + (size_t)(mbf * 128 + ktf) * A_TILE,
                 A_TILE, fb);
        bulk_g2s(sdst + A_TILE,
                 (const char*)g_Bpack + (size_t)(nbf * 128 + ktf) * B_TILE,
                 B_TILE, fb);
    };
    if (tid == 0) {
        for (int f = 0; f < NST && f < GI; f++) fill(f);
    }

    // per-thread ldmatrix geometry
    int g = lane >> 3, tr = lane & 7;
    int m_warp = (wid & 1) * 64;
    int n_warp = (wid >> 1) * 64;
    int aRow0 = m_warp + (g & 1) * 8 + tr;
    int aH = g >> 1;
    int bRow0 = n_warp + (g >> 1) * 8 + tr;
    int bH = g & 1;

    for (int tile_i = 0; tile_i < ntiles; tile_i++) {
        int tile = p + tile_i * P;
        int mb = tile & 31, nb = tile >> 5;

        float acc[4][8][4];
#pragma unroll
        for (int i = 0; i < 4; i++)
#pragma unroll
            for (int j = 0; j < 8; j++)
#pragma unroll
                for (int k = 0; k < 4; k++) acc[i][j][k] = 0.f;

        for (int kt = 0; kt < KT; kt++) {
            int gi = tile_i * KT + kt;
            int st = gi & (NST - 1);
            mbar_wait(sb + st * 8, (gi >> 3) & 1);
            uint32_t As = sb + SMEM_OFF + st * STAGE_BYTES;
            uint32_t Bs = As + A_TILE;

            // ks = 0
            uint32_t a0[4][4], b0[8][2];
#pragma unroll
            for (int mt = 0; mt < 4; mt++) {
                int r = aRow0 + mt * 16;
                int c = aH ^ ((r >> 1) & 3);
                ldsm4(a0[mt], As + r * 64 + c * 16);
            }
#pragma unroll
            for (int nt2 = 0; nt2 < 4; nt2++) {
                int r = bRow0 + nt2 * 16;
                int c = bH ^ ((r >> 1) & 3);
                uint32_t q[4];
                ldsm4(q, Bs + r * 64 + c * 16);
                b0[nt2 * 2][0] = q[0]; b0[nt2 * 2][1] = q[1];
                b0[nt2 * 2 + 1][0] = q[2]; b0[nt2 * 2 + 1][1] = q[3];
            }
#pragma unroll
            for (int mt = 0; mt < 4; mt++)
#pragma unroll
                for (int nt = 0; nt < 8; nt++)
                    mma16816(acc[mt][nt], a0[mt], b0[nt]);

            // ks = 1: load frags, release the stage, then MMA
            uint32_t a1[4][4], b1[8][2];
#pragma unroll
            for (int mt = 0; mt < 4; mt++) {
                int r = aRow0 + mt * 16;
                int c = (2 + aH) ^ ((r >> 1) & 3);
                ldsm4(a1[mt], As + r * 64 + c * 16);
            }
#pragma unroll
            for (int nt2 = 0; nt2 < 4; nt2++) {
                int r = bRow0 + nt2 * 16;
                int c = (2 + bH) ^ ((r >> 1) & 3);
                uint32_t q[4];
                ldsm4(q, Bs + r * 64 + c * 16);
                b1[nt2 * 2][0] = q[0]; b1[nt2 * 2][1] = q[1];
                b1[nt2 * 2 + 1][0] = q[2]; b1[nt2 * 2 + 1][1] = q[3];
            }
            if (lane == 0) mbar_arrive(sb + 64 + st * 8);   // stage consumed
#pragma unroll
            for (int mt = 0; mt < 4; mt++)
#pragma unroll
                for (int nt = 0; nt < 8; nt++)
                    mma16816(acc[mt][nt], a1[mt], b1[nt]);

            if (tid == 0) {
                int f = gi + NST;
                if (f < GI) fill(f);
            }
        }

        // epilogue (no syncs needed: regs only, stage smem untouched)
        int m0 = mb * BM + m_warp;
        int n0 = nb * BN + n_warp;
        float2 bv[8];
#pragma unroll
        for (int nt = 0; nt < 8; nt++)
            bv[nt] = *reinterpret_cast<const float2*>(
                &bias[n0 + nt * 8 + (lane & 3) * 2]);
#pragma unroll
        for (int mt = 0; mt < 4; mt++) {
#pragma unroll
            for (int nt = 0; nt < 8; nt++) {
                int row = m0 + mt * 16 + (lane >> 2);
                int col = n0 + nt * 8 + (lane & 3) * 2;
                float2 v0 = make_float2(acc[mt][nt][0] + bv[nt].x,
                                        acc[mt][nt][1] + bv[nt].y);
                float2 v1 = make_float2(acc[mt][nt][2] + bv[nt].x,
                                        acc[mt][nt][3] + bv[nt].y);
                *reinterpret_cast<float2*>(&C[(size_t)row * N_DIM + col]) = v0;
                *reinterpret_cast<float2*>(&C[(size_t)(row + 8) * N_DIM + col]) = v1;
            }
        }
    }
}

// ---------------------------------------------------------------------------
// Launch
// ---------------------------------------------------------------------------
extern "C" void kernel_launch(void* const* d_in, const int* in_sizes, int n_in,
                              void* d_out, int out_size) {
    const float* A    = (const float*)d_in[0];
    const int*   B    = (const int*)  d_in[1];
    const float* s    = (const float*)d_in[2];
    const float* bias = (const float*)d_in[3];
    float* C = (float*)d_out;

    cudaFuncSetAttribute(gemm_hmma_kernel,
                         cudaFuncAttributeMaxDynamicSharedMemorySize, SMEM_BYTES);

    int nsm = 148;
    cudaDeviceGetAttribute(&nsm, cudaDevAttrMultiProcessorCount, 0);

    convA_kernel<<<(M_DIM * 512) / 256, 256>>>(A);
    dequant_kernel<<<((K_DIM / 16) * N_DIM) / 256, 256>>>(B, s);
    gemm_hmma_kernel<<<nsm, 256, SMEM_BYTES>>>(bias, C);
}